// round 13
// baseline (speedup 1.0000x reference)
#include <cuda_runtime.h>
#include <cuda_fp16.h>
#include <math.h>
#include <stdint.h>

#define LEVELS 9
#define N_NODES 87381          // (4^9-1)/3
#define N_INTERNAL 21845
#define LEAF_START 21845
#define LEAF_N 65536

// ---------------- scratch (device globals: allocation-free rule) ----------------
__device__ __half g_xH[(size_t)N_NODES * 256];         // fp16 x
__device__ __half g_hH[(size_t)N_NODES * 256];         // fp16 h
__device__ __half g_xioufq[(size_t)N_INTERNAL * 1280]; // internal [iou(768)|f(256)|q(256)] fp16
__device__ __half g_kv[(size_t)65536 * 512];           // fp16 k|v
__device__ __half g_aoutH[(size_t)16384 * 256];        // fp16 attention out
__device__ __half g_hu[(size_t)16384 * 1024];          // fp16 h_iou|h_f
// packed weights, transposed [N][256], fp16
__device__ __half g_Wcat2T[1280 * 256];                // [iou|f|q]
__device__ float  g_bcat2[1280];
__device__ __half g_WleafT[1024 * 256];                // PERMUTED leaf [i16|o16|u16|pad16]
__device__ __half g_WkvT[512 * 256];
__device__ float  g_bkv[512];
__device__ __half g_UcatT[1024 * 256];                 // [Uiou|Uf] transposed
__device__ __half g_WlR[257 * 256];                    // Wl row-major fp16 + row 256 = bl
__device__ float  g_WcombRaw[257 * 1024];              // [Wl;bl]@U fp32 [k][n]
__device__ __half g_WcombT[1024 * 256];                // transposed fp16
__device__ float  g_bcomb[1024];                       // bl@U + bU (fp32)
__device__ float  g_zero[1280];                        // stays zero

__device__ __forceinline__ float sigmoidf_(float x) { return 1.0f / (1.0f + expf(-x)); }

__device__ __forceinline__ void mma_fp16(float c[4],
                                         uint32_t a0, uint32_t a1, uint32_t a2, uint32_t a3,
                                         uint32_t b0, uint32_t b1) {
    asm volatile("mma.sync.aligned.m16n8k16.row.col.f32.f16.f16.f32 "
                 "{%0,%1,%2,%3}, {%4,%5,%6,%7}, {%8,%9}, {%0,%1,%2,%3};\n"
                 : "+f"(c[0]), "+f"(c[1]), "+f"(c[2]), "+f"(c[3])
                 : "r"(a0), "r"(a1), "r"(a2), "r"(a3), "r"(b0), "r"(b1));
}

__device__ __forceinline__ void ldsm_x4(uint32_t& r0, uint32_t& r1, uint32_t& r2, uint32_t& r3,
                                        uint32_t addr) {
    asm volatile("ldmatrix.sync.aligned.m8n8.x4.shared.b16 {%0,%1,%2,%3}, [%4];"
                 : "=r"(r0), "=r"(r1), "=r"(r2), "=r"(r3) : "r"(addr));
}

// ---------------- weight packing ----------------
__global__ void pack_weights(const float* __restrict__ W_iou, const float* __restrict__ b_iou,
                             const float* __restrict__ W_f,   const float* __restrict__ b_f,
                             const float* __restrict__ Wq,    const float* __restrict__ bq,
                             const float* __restrict__ Wk,    const float* __restrict__ bk,
                             const float* __restrict__ Wv,    const float* __restrict__ bv,
                             const float* __restrict__ Wl,    const float* __restrict__ bl,
                             const float* __restrict__ Uiou_w,
                             const float* __restrict__ Uf_w)
{
    int idx = blockIdx.x * blockDim.x + threadIdx.x;
    if (idx >= 256 * 1280) return;
    int r = idx / 1280, c = idx % 1280;
    float w2;
    if (c < 768)       w2 = W_iou[r * 768 + c];
    else if (c < 1024) w2 = W_f[r * 256 + (c - 768)];
    else               w2 = Wq[r * 256 + (c - 1024)];
    g_Wcat2T[c * 256 + r] = __float2half(w2);
    if (c < 1024) {
        float wu = (c < 768) ? Uiou_w[r * 768 + c] : Uf_w[r * 256 + (c - 768)];
        g_UcatT[c * 256 + r] = __float2half(wu);
        // permuted leaf weights: c = newcol
        int b = c >> 7, w = (c >> 6) & 1, comp = (c & 63) >> 4, id16 = c & 15;
        int d = b * 32 + w * 16 + id16;
        float wl = (comp < 3) ? W_iou[r * 768 + comp * 256 + d] : 0.0f;
        g_WleafT[c * 256 + r] = __float2half(wl);
    }
    if (c < 512) {
        float wk = (c < 256) ? Wk[r * 256 + c] : Wv[r * 256 + (c - 256)];
        g_WkvT[c * 256 + r] = __float2half(wk);
    }
    if (c < 256) g_WlR[r * 256 + c] = __float2half(Wl[r * 256 + c]);
    if (r == 0) {
        if (c < 768)       g_bcat2[c] = b_iou[c];
        else if (c < 1024) g_bcat2[c] = b_f[c - 768];
        else               g_bcat2[c] = bq[c - 1024];
        if (c < 512) g_bkv[c] = (c < 256) ? bk[c] : bv[c - 256];
        if (c < 256) g_WlR[256 * 256 + c] = __float2half(bl[c]);  // bl as extra row
    }
}

__global__ void finish_comb(const float* __restrict__ Uiou_b, const float* __restrict__ Uf_b)
{
    int idx = blockIdx.x * blockDim.x + threadIdx.x;
    if (idx >= 256 * 1024) return;
    int k = idx >> 10, n = idx & 1023;
    g_WcombT[n * 256 + k] = __float2half(g_WcombRaw[k * 1024 + n]);
    if (k == 0)
        g_bcomb[n] = g_WcombRaw[256 * 1024 + n] + ((n < 768) ? Uiou_b[n] : Uf_b[n - 768]);
}

__global__ void convert_x_kernel(const float* __restrict__ x)
{
    size_t i = (size_t)blockIdx.x * blockDim.x + threadIdx.x;
    if (i >= (size_t)N_NODES * 64) return;
    float4 v = reinterpret_cast<const float4*>(x)[i];
    __half2 h0 = __floats2half2_rn(v.x, v.y);
    __half2 h1 = __floats2half2_rn(v.z, v.w);
    uint2 pack;
    pack.x = *reinterpret_cast<uint32_t*>(&h0);
    pack.y = *reinterpret_cast<uint32_t*>(&h1);
    reinterpret_cast<uint2*>(g_xH)[i] = pack;
}

// -------- FP16 tensor-core GEMM, cp.async 4-stage pipeline (wait_group 2) --------
#define STAGES 4
#define SROWH 40
#define STGH_BYTES (256 * SROWH * 2)      // 20480
#define GEMM_SMEM (STAGES * STGH_BYTES)   // 81920

__device__ __forceinline__ void issue_load(uint32_t sbase, int st,
                                           const __half* __restrict__ A,
                                           const __half* __restrict__ Bt,
                                           int row0, int col0, int M, int k0, int tid)
{
    uint32_t so = sbase + st * STGH_BYTES;
    int row4 = tid >> 2;
    int ch   = (tid & 3) * 8;
    #pragma unroll
    for (int i = 0; i < 4; i++) {
        int r = row4 + 32 * i;
        bool ok = (row0 + r) < M;
        uint32_t da = so + (r * SROWH + ch) * 2;
        const __half* ga = A + (size_t)(ok ? (row0 + r) : 0) * 256 + k0 + ch;
        int sz = ok ? 16 : 0;
        asm volatile("cp.async.cg.shared.global [%0], [%1], 16, %2;"
                     :: "r"(da), "l"(ga), "r"(sz) : "memory");
        uint32_t db = so + ((128 + r) * SROWH + ch) * 2;
        const __half* gb = Bt + (size_t)(col0 + r) * 256 + k0 + ch;
        asm volatile("cp.async.cg.shared.global [%0], [%1], 16;"
                     :: "r"(db), "l"(gb) : "memory");
    }
}

__device__ __forceinline__ void compute_stage(uint32_t soff,
                                              const uint32_t aoff[4], const uint32_t boff[4],
                                              float acc[4][8][4])
{
    #pragma unroll
    for (int kk = 0; kk < 32; kk += 16) {
        uint32_t af[4][4];
        #pragma unroll
        for (int mi = 0; mi < 4; mi++)
            ldsm_x4(af[mi][0], af[mi][1], af[mi][2], af[mi][3], soff + aoff[mi] + kk * 2);
        uint32_t bf[8][2];
        #pragma unroll
        for (int np = 0; np < 4; np++)
            ldsm_x4(bf[2 * np][0], bf[2 * np][1], bf[2 * np + 1][0], bf[2 * np + 1][1],
                    soff + boff[np] + kk * 2);
        #pragma unroll
        for (int mi = 0; mi < 4; mi++)
            #pragma unroll
            for (int ni = 0; ni < 8; ni++)
                mma_fp16(acc[mi][ni],
                         af[mi][0], af[mi][1], af[mi][2], af[mi][3],
                         bf[ni][0], bf[ni][1]);
    }
}

// shared mainloop prologue+loop (declares tid/lane/warp/wr/wc/g/r8/gid/tig/row0/col0/acc)
#define GEMM_BODY()                                                                \
    extern __shared__ uint32_t sm[];                                               \
    int tid  = threadIdx.x;                                                        \
    int lane = tid & 31;                                                           \
    int warp = tid >> 5;                                                           \
    int wr = warp >> 1, wc = warp & 1;                                             \
    int g  = lane >> 3, r8 = lane & 7;                                             \
    int gid = lane >> 2, tig = lane & 3;                                           \
    int row0 = blockIdx.y * 128;                                                   \
    int col0 = blockIdx.x * 128;                                                   \
    uint32_t sbase = (uint32_t)__cvta_generic_to_shared(sm);                       \
    uint32_t aoff[4], boff[4];                                                     \
    _Pragma("unroll")                                                              \
    for (int mi = 0; mi < 4; mi++) {                                               \
        int row = wr * 64 + mi * 16 + ((g & 1) << 3) + r8;                         \
        aoff[mi] = (row * SROWH + ((g >> 1) << 3)) * 2;                            \
    }                                                                              \
    _Pragma("unroll")                                                              \
    for (int np = 0; np < 4; np++) {                                               \
        int row = 128 + wc * 64 + np * 16 + ((g >> 1) << 3) + r8;                  \
        boff[np] = (row * SROWH + ((g & 1) << 3)) * 2;                             \
    }                                                                              \
    float acc[4][8][4];                                                            \
    _Pragma("unroll")                                                              \
    for (int mi = 0; mi < 4; mi++)                                                 \
        _Pragma("unroll")                                                          \
        for (int ni = 0; ni < 8; ni++)                                             \
            _Pragma("unroll")                                                      \
            for (int t = 0; t < 4; t++) acc[mi][ni][t] = 0.0f;                     \
    issue_load(sbase, 0, A, Bt, row0, col0, M, 0, tid);                            \
    asm volatile("cp.async.commit_group;" ::: "memory");                           \
    issue_load(sbase, 1, A, Bt, row0, col0, M, 32, tid);                           \
    asm volatile("cp.async.commit_group;" ::: "memory");                           \
    issue_load(sbase, 2, A, Bt, row0, col0, M, 64, tid);                           \
    asm volatile("cp.async.commit_group;" ::: "memory");                           \
    _Pragma("unroll")                                                              \
    for (int it = 0; it < 8; it++) {                                               \
        asm volatile("cp.async.wait_group 2;" ::: "memory");                       \
        __syncthreads();                                                           \
        compute_stage(sbase + (it % STAGES) * STGH_BYTES, aoff, boff, acc);        \
        if (it + 3 < 8)                                                            \
            issue_load(sbase, (it + 3) % STAGES, A, Bt, row0, col0, M, (it + 3) * 32, tid); \
        asm volatile("cp.async.commit_group;" ::: "memory");                       \
    }

template <bool HALF_OUT>
__global__ void __launch_bounds__(128) gemm_fp16(const __half* __restrict__ A,
                                                 const __half* __restrict__ Bt,
                                                 const float* __restrict__ bias,
                                                 void* __restrict__ Cv, int M, int N)
{
    GEMM_BODY();
    float*  Cf = (float*)Cv;
    __half* Ch = (__half*)Cv;
    #pragma unroll
    for (int mi = 0; mi < 4; mi++) {
        int rbase = row0 + wr * 64 + mi * 16 + gid;
        #pragma unroll
        for (int ni = 0; ni < 8; ni++) {
            int c = col0 + wc * 64 + ni * 8 + 2 * tig;
            float b0 = bias[c], b1 = bias[c + 1];
            if (rbase < M) {
                float v0 = acc[mi][ni][0] + b0, v1 = acc[mi][ni][1] + b1;
                if (HALF_OUT)
                    *reinterpret_cast<__half2*>(Ch + (size_t)rbase * N + c) = __floats2half2_rn(v0, v1);
                else
                    *reinterpret_cast<float2*>(Cf + (size_t)rbase * N + c) = make_float2(v0, v1);
            }
            if (rbase + 8 < M) {
                float v2 = acc[mi][ni][2] + b0, v3 = acc[mi][ni][3] + b1;
                if (HALF_OUT)
                    *reinterpret_cast<__half2*>(Ch + (size_t)(rbase + 8) * N + c) = __floats2half2_rn(v2, v3);
                else
                    *reinterpret_cast<float2*>(Cf + (size_t)(rbase + 8) * N + c) = make_float2(v2, v3);
            }
        }
    }
}

// ---------- leaf GEMM with write-only gate epilogue (permuted WleafT, N=1024) ----
__global__ void __launch_bounds__(128) gemm_leaf_gate(const __half* __restrict__ A,
                                                      const __half* __restrict__ Bt,
                                                      float* __restrict__ outH,
                                                      float* __restrict__ outC,
                                                      int M)
{
    GEMM_BODY();
    #pragma unroll
    for (int mi = 0; mi < 4; mi++) {
        int rloc0 = row0 + wr * 64 + mi * 16 + gid;
        #pragma unroll
        for (int s = 0; s < 2; s++) {
            int d = blockIdx.x * 32 + wc * 16 + s * 8 + 2 * tig;
            float bi0 = g_bcat2[d],        bi1 = g_bcat2[d + 1];
            float bo0 = g_bcat2[256 + d],  bo1 = g_bcat2[257 + d];
            float bu0 = g_bcat2[512 + d],  bu1 = g_bcat2[513 + d];
            #pragma unroll
            for (int hrow = 0; hrow < 2; hrow++) {
                int rloc = rloc0 + 8 * hrow;
                int t0 = 2 * hrow, t1 = 2 * hrow + 1;
                float i0 = acc[mi][0 + s][t0] + bi0, i1 = acc[mi][0 + s][t1] + bi1;
                float o0 = acc[mi][2 + s][t0] + bo0, o1 = acc[mi][2 + s][t1] + bo1;
                float u0 = acc[mi][4 + s][t0] + bu0, u1 = acc[mi][4 + s][t1] + bu1;
                float c0 = sigmoidf_(i0) * tanhf(u0);
                float c1 = sigmoidf_(i1) * tanhf(u1);
                float h0 = sigmoidf_(o0) * tanhf(c0);
                float h1 = sigmoidf_(o1) * tanhf(c1);
                size_t base = (size_t)(LEAF_START + rloc) * 256 + d;
                *reinterpret_cast<float2*>(outH + base) = make_float2(h0, h1);
                *reinterpret_cast<float2*>(outC + base) = make_float2(c0, c1);
                *reinterpret_cast<__half2*>(g_hH + base) = __floats2half2_rn(h0, h1);
            }
        }
    }
}

__device__ __forceinline__ float4 load_h4(const __half* p) {
    uint2 raw = *reinterpret_cast<const uint2*>(p);
    __half2 a = *reinterpret_cast<__half2*>(&raw.x);
    __half2 b = *reinterpret_cast<__half2*>(&raw.y);
    float2 fa = __half22float2(a), fb = __half22float2(b);
    return make_float4(fa.x, fa.y, fb.x, fb.y);
}

// ---------------- attention: warp per (node, head) ----------------
__global__ void attn_kernel(int s0)
{
    int j = blockIdx.x;
    int node = s0 + j;
    int w = threadIdx.x >> 5;
    int t = threadIdx.x & 31;
    const float scale = 0.17677669529663687f; // 1/sqrt(32)
    float qv = __half2float(g_xioufq[(size_t)node * 1280 + 1024 + w * 32 + t]);
    float logit[4];
    #pragma unroll
    for (int k = 0; k < 4; k++) {
        float kk = __half2float(g_kv[(size_t)(4 * j + k) * 512 + w * 32 + t]);
        float p = qv * kk;
        #pragma unroll
        for (int off = 16; off; off >>= 1) p += __shfl_xor_sync(0xffffffffu, p, off);
        logit[k] = p * scale;
    }
    float m = fmaxf(fmaxf(logit[0], logit[1]), fmaxf(logit[2], logit[3]));
    float e[4], s = 0.f;
    #pragma unroll
    for (int k = 0; k < 4; k++) { e[k] = expf(logit[k] - m); s += e[k]; }
    float inv = 1.0f / s;
    float o = 0.f;
    #pragma unroll
    for (int k = 0; k < 4; k++)
        o += e[k] * inv * __half2float(g_kv[(size_t)(4 * j + k) * 512 + 256 + w * 32 + t]);
    g_aoutH[(size_t)j * 256 + w * 32 + t] = __float2half(o);
}

// ---------------- internal-level gates ----------------
__global__ void gate_kernel(float* __restrict__ outH, float* __restrict__ outC,
                            int s0, int cs, int n)
{
    int t  = threadIdx.x;
    int jj = blockIdx.x * 4 + (t >> 6);
    if (jj >= n) return;
    int d  = (t & 63) * 4;
    int node = s0 + jj;
    const __half* xr = g_xioufq + (size_t)node * 1280;
    const __half* hr = g_hu + (size_t)jj * 1024;
    float4 i4 = load_h4(xr + d);
    float4 o4 = load_h4(xr + 256 + d);
    float4 u4 = load_h4(xr + 512 + d);
    float4 f4 = load_h4(xr + 768 + d);
    float4 hi = load_h4(hr + d);
    float4 ho = load_h4(hr + 256 + d);
    float4 hu4 = load_h4(hr + 512 + d);
    float4 hf = load_h4(hr + 768 + d);
    float4 cs4 = make_float4(0.f, 0.f, 0.f, 0.f);
    #pragma unroll
    for (int k = 0; k < 4; k++) {
        float4 cc = *reinterpret_cast<const float4*>(outC + (size_t)(cs + 4 * jj + k) * 256 + d);
        cs4.x += cc.x; cs4.y += cc.y; cs4.z += cc.z; cs4.w += cc.w;
    }
    float4 c4, h4;
    __half hh[4];
    #pragma unroll
    for (int q = 0; q < 4; q++) {
        float i = (&i4.x)[q] + (&hi.x)[q];
        float o = (&o4.x)[q] + (&ho.x)[q];
        float u = (&u4.x)[q] + (&hu4.x)[q];
        float f = sigmoidf_((&f4.x)[q] + (&hf.x)[q]);
        float c = sigmoidf_(i) * tanhf(u) + f * (&cs4.x)[q];
        float h = sigmoidf_(o) * tanhf(c);
        (&c4.x)[q] = c; (&h4.x)[q] = h; hh[q] = __float2half(h);
    }
    size_t base = (size_t)node * 256 + d;
    *reinterpret_cast<float4*>(outH + base) = h4;
    *reinterpret_cast<float4*>(outC + base) = c4;
    *reinterpret_cast<uint2*>(g_hH + base) = *reinterpret_cast<uint2*>(hh);
}

// ---------------- host launch ----------------
extern "C" void kernel_launch(void* const* d_in, const int* in_sizes, int n_in,
                              void* d_out, int out_size)
{
    const float* x      = (const float*)d_in[0];
    const float* W_iou  = (const float*)d_in[1];
    const float* b_iou  = (const float*)d_in[2];
    const float* W_f    = (const float*)d_in[3];
    const float* b_f    = (const float*)d_in[4];
    const float* Wq     = (const float*)d_in[5];
    const float* bq     = (const float*)d_in[6];
    const float* Wk     = (const float*)d_in[7];
    const float* bk     = (const float*)d_in[8];
    const float* Wv     = (const float*)d_in[9];
    const float* bv     = (const float*)d_in[10];
    const float* Wl     = (const float*)d_in[11];
    const float* bl     = (const float*)d_in[12];
    const float* Uiou_w = (const float*)d_in[13];
    const float* Uiou_b = (const float*)d_in[14];
    const float* Uf_w   = (const float*)d_in[15];
    const float* Uf_b   = (const float*)d_in[16];

    float* outH = (float*)d_out;
    float* outC = outH + (size_t)N_NODES * 256;

    static bool attr_set = false;
    if (!attr_set) {
        cudaFuncSetAttribute(gemm_fp16<false>, cudaFuncAttributeMaxDynamicSharedMemorySize, GEMM_SMEM);
        cudaFuncSetAttribute(gemm_fp16<true>,  cudaFuncAttributeMaxDynamicSharedMemorySize, GEMM_SMEM);
        cudaFuncSetAttribute(gemm_leaf_gate,   cudaFuncAttributeMaxDynamicSharedMemorySize, GEMM_SMEM);
        attr_set = true;
    }

    __half *p_xH, *p_hH, *p_aoutH, *p_W2, *p_Wleaf, *p_Wkv, *p_Uc, *p_WlR, *p_WcT;
    __half *p_xioufq, *p_kv, *p_hu;
    float *p_b2, *p_bkv, *p_WcR, *p_bc, *p_zero;
    cudaGetSymbolAddress((void**)&p_xH,     g_xH);
    cudaGetSymbolAddress((void**)&p_hH,     g_hH);
    cudaGetSymbolAddress((void**)&p_aoutH,  g_aoutH);
    cudaGetSymbolAddress((void**)&p_xioufq, g_xioufq);
    cudaGetSymbolAddress((void**)&p_kv,     g_kv);
    cudaGetSymbolAddress((void**)&p_hu,     g_hu);
    cudaGetSymbolAddress((void**)&p_W2,     g_Wcat2T);
    cudaGetSymbolAddress((void**)&p_b2,     g_bcat2);
    cudaGetSymbolAddress((void**)&p_Wleaf,  g_WleafT);
    cudaGetSymbolAddress((void**)&p_Wkv,    g_WkvT);
    cudaGetSymbolAddress((void**)&p_bkv,    g_bkv);
    cudaGetSymbolAddress((void**)&p_Uc,     g_UcatT);
    cudaGetSymbolAddress((void**)&p_WlR,    g_WlR);
    cudaGetSymbolAddress((void**)&p_WcR,    g_WcombRaw);
    cudaGetSymbolAddress((void**)&p_WcT,    g_WcombT);
    cudaGetSymbolAddress((void**)&p_bc,     g_bcomb);
    cudaGetSymbolAddress((void**)&p_zero,   g_zero);

    static const int starts[LEVELS + 1] =
        {0, 1, 5, 21, 85, 341, 1365, 5461, 21845, 87381};

    pack_weights<<<(256 * 1280 + 255) / 256, 256>>>(
        W_iou, b_iou, W_f, b_f, Wq, bq, Wk, bk, Wv, bv, Wl, bl, Uiou_w, Uf_w);

    // [Wcomb; bl@U] = [Wl; bl] @ U  (257 x 1024 fp32), then transpose+convert + bcomb
    {
        dim3 grid(1024 / 128, 3);
        gemm_fp16<false><<<grid, 128, GEMM_SMEM>>>(p_WlR, p_Uc, p_zero, p_WcR, 257, 1024);
    }
    finish_comb<<<(256 * 1024 + 255) / 256, 256>>>(Uiou_b, Uf_b);

    convert_x_kernel<<<(N_NODES * 64 + 255) / 256, 256>>>(x);

    // fused leaf GEMM + gates (permuted weights, N=1024, write-only epilogue)
    {
        dim3 grid(8, LEAF_N / 128);
        gemm_leaf_gate<<<grid, 128, GEMM_SMEM>>>(p_xH + (size_t)LEAF_START * 256,
                                                 p_Wleaf, outH, outC, LEAF_N);
    }
    // internal iou|f|q (N=1280, fp16 out)
    {
        dim3 grid(1280 / 128, (N_INTERNAL + 127) / 128);
        gemm_fp16<true><<<grid, 128, GEMM_SMEM>>>(p_xH, p_W2, p_b2, p_xioufq, N_INTERNAL, 1280);
    }

    for (int l = LEVELS - 2; l >= 0; --l) {
        int n  = 1 << (2 * l);
        int s0 = starts[l];
        int cs = starts[l + 1];
        int nc = 4 * n;

        {
            dim3 grid(512 / 128, (nc + 127) / 128);
            gemm_fp16<true><<<grid, 128, GEMM_SMEM>>>(p_hH + (size_t)cs * 256,
                                                      p_Wkv, p_bkv, p_kv, nc, 512);
        }
        attn_kernel<<<n, 256>>>(s0);
        {
            dim3 grid(1024 / 128, (n + 127) / 128);
            gemm_fp16<true><<<grid, 128, GEMM_SMEM>>>(p_aoutH, p_WcT, p_bc, p_hu, n, 1024);
        }
        gate_kernel<<<(n + 3) / 4, 256>>>(outH, outC, s0, cs, n);
    }
}

// round 17
// speedup vs baseline: 1.5439x; 1.5439x over previous
#include <cuda_runtime.h>
#include <cuda_fp16.h>
#include <math.h>
#include <stdint.h>

#define LEVELS 9
#define N_NODES 87381          // (4^9-1)/3
#define N_INTERNAL 21845
#define LEAF_START 21845
#define LEAF_N 65536

// ---------------- scratch (device globals: allocation-free rule) ----------------
__device__ __half g_xH[(size_t)N_NODES * 256];         // fp16 x
__device__ __half g_hH[(size_t)N_NODES * 256];         // fp16 h
__device__ __half g_xioufq[(size_t)N_INTERNAL * 1280]; // internal [iou(768)|f(256)|q(256)] fp16
__device__ __half g_kv[(size_t)65536 * 512];           // fp16 k|v
__device__ __half g_aoutH[(size_t)16384 * 256];        // fp16 attention out
__device__ __half g_hu[(size_t)16384 * 1024];          // fp16 h_iou|h_f
// packed weights, transposed [N][256], fp16
__device__ __half g_Wcat2T[1280 * 256];                // [iou|f|q]
__device__ float  g_bcat2[1280];
__device__ __half g_WleafT[1024 * 256];                // PERMUTED leaf [i16|o16|u16|pad16]
__device__ __half g_WkvT[512 * 256];
__device__ float  g_bkv[512];
__device__ __half g_UcatT[1024 * 256];                 // [Uiou|Uf] transposed
__device__ __half g_WlR[257 * 256];                    // Wl row-major fp16 + row 256 = bl
__device__ float  g_WcombRaw[257 * 1024];              // [Wl;bl]@U fp32 [k][n]
__device__ __half g_WcombT[1024 * 256];                // transposed fp16
__device__ float  g_bcomb[1024];                       // bl@U + bU (fp32)
__device__ float  g_zero[1280];                        // stays zero

__device__ __forceinline__ float sigmoidf_(float x) { return 1.0f / (1.0f + expf(-x)); }

__device__ __forceinline__ void mma_fp16(float c[4],
                                         uint32_t a0, uint32_t a1, uint32_t a2, uint32_t a3,
                                         uint32_t b0, uint32_t b1) {
    asm volatile("mma.sync.aligned.m16n8k16.row.col.f32.f16.f16.f32 "
                 "{%0,%1,%2,%3}, {%4,%5,%6,%7}, {%8,%9}, {%0,%1,%2,%3};\n"
                 : "+f"(c[0]), "+f"(c[1]), "+f"(c[2]), "+f"(c[3])
                 : "r"(a0), "r"(a1), "r"(a2), "r"(a3), "r"(b0), "r"(b1));
}

__device__ __forceinline__ void ldsm_x4(uint32_t& r0, uint32_t& r1, uint32_t& r2, uint32_t& r3,
                                        uint32_t addr) {
    asm volatile("ldmatrix.sync.aligned.m8n8.x4.shared.b16 {%0,%1,%2,%3}, [%4];"
                 : "=r"(r0), "=r"(r1), "=r"(r2), "=r"(r3) : "r"(addr));
}

// ---------------- weight packing ----------------
__global__ void pack_weights(const float* __restrict__ W_iou, const float* __restrict__ b_iou,
                             const float* __restrict__ W_f,   const float* __restrict__ b_f,
                             const float* __restrict__ Wq,    const float* __restrict__ bq,
                             const float* __restrict__ Wk,    const float* __restrict__ bk,
                             const float* __restrict__ Wv,    const float* __restrict__ bv,
                             const float* __restrict__ Wl,    const float* __restrict__ bl,
                             const float* __restrict__ Uiou_w,
                             const float* __restrict__ Uf_w)
{
    int idx = blockIdx.x * blockDim.x + threadIdx.x;
    if (idx >= 256 * 1280) return;
    int r = idx / 1280, c = idx % 1280;
    float w2;
    if (c < 768)       w2 = W_iou[r * 768 + c];
    else if (c < 1024) w2 = W_f[r * 256 + (c - 768)];
    else               w2 = Wq[r * 256 + (c - 1024)];
    g_Wcat2T[c * 256 + r] = __float2half(w2);
    if (c < 1024) {
        float wu = (c < 768) ? Uiou_w[r * 768 + c] : Uf_w[r * 256 + (c - 768)];
        g_UcatT[c * 256 + r] = __float2half(wu);
        // permuted leaf weights: c = newcol
        int b = c >> 7, w = (c >> 6) & 1, comp = (c & 63) >> 4, id16 = c & 15;
        int d = b * 32 + w * 16 + id16;
        float wl = (comp < 3) ? W_iou[r * 768 + comp * 256 + d] : 0.0f;
        g_WleafT[c * 256 + r] = __float2half(wl);
    }
    if (c < 512) {
        float wk = (c < 256) ? Wk[r * 256 + c] : Wv[r * 256 + (c - 256)];
        g_WkvT[c * 256 + r] = __float2half(wk);
    }
    if (c < 256) g_WlR[r * 256 + c] = __float2half(Wl[r * 256 + c]);
    if (r == 0) {
        if (c < 768)       g_bcat2[c] = b_iou[c];
        else if (c < 1024) g_bcat2[c] = b_f[c - 768];
        else               g_bcat2[c] = bq[c - 1024];
        if (c < 512) g_bkv[c] = (c < 256) ? bk[c] : bv[c - 256];
        if (c < 256) g_WlR[256 * 256 + c] = __float2half(bl[c]);  // bl as extra row
    }
}

__global__ void finish_comb(const float* __restrict__ Uiou_b, const float* __restrict__ Uf_b)
{
    int idx = blockIdx.x * blockDim.x + threadIdx.x;
    if (idx >= 256 * 1024) return;
    int k = idx >> 10, n = idx & 1023;
    g_WcombT[n * 256 + k] = __float2half(g_WcombRaw[k * 1024 + n]);
    if (k == 0)
        g_bcomb[n] = g_WcombRaw[256 * 1024 + n] + ((n < 768) ? Uiou_b[n] : Uf_b[n - 768]);
}

__global__ void convert_x_kernel(const float* __restrict__ x)
{
    size_t i = (size_t)blockIdx.x * blockDim.x + threadIdx.x;
    if (i >= (size_t)N_NODES * 64) return;
    float4 v = reinterpret_cast<const float4*>(x)[i];
    __half2 h0 = __floats2half2_rn(v.x, v.y);
    __half2 h1 = __floats2half2_rn(v.z, v.w);
    uint2 pack;
    pack.x = *reinterpret_cast<uint32_t*>(&h0);
    pack.y = *reinterpret_cast<uint32_t*>(&h1);
    reinterpret_cast<uint2*>(g_xH)[i] = pack;
}

// ---------------- FP16 tensor-core GEMM, cp.async 3-stage pipeline ----------------
#define STAGES 3
#define SROWH 40
#define STGH_BYTES (256 * SROWH * 2)      // 20480
#define GEMM_SMEM (STAGES * STGH_BYTES)   // 61440

__device__ __forceinline__ void issue_load(uint32_t sbase, int st,
                                           const __half* __restrict__ A,
                                           const __half* __restrict__ Bt,
                                           int row0, int col0, int M, int k0, int tid)
{
    uint32_t so = sbase + st * STGH_BYTES;
    int row4 = tid >> 2;
    int ch   = (tid & 3) * 8;
    #pragma unroll
    for (int i = 0; i < 4; i++) {
        int r = row4 + 32 * i;
        bool ok = (row0 + r) < M;
        uint32_t da = so + (r * SROWH + ch) * 2;
        const __half* ga = A + (size_t)(ok ? (row0 + r) : 0) * 256 + k0 + ch;
        int sz = ok ? 16 : 0;
        asm volatile("cp.async.cg.shared.global [%0], [%1], 16, %2;"
                     :: "r"(da), "l"(ga), "r"(sz) : "memory");
        uint32_t db = so + ((128 + r) * SROWH + ch) * 2;
        const __half* gb = Bt + (size_t)(col0 + r) * 256 + k0 + ch;
        asm volatile("cp.async.cg.shared.global [%0], [%1], 16;"
                     :: "r"(db), "l"(gb) : "memory");
    }
}

__device__ __forceinline__ void compute_stage(uint32_t soff,
                                              const uint32_t aoff[4], const uint32_t boff[4],
                                              float acc[4][8][4])
{
    #pragma unroll
    for (int kk = 0; kk < 32; kk += 16) {
        uint32_t af[4][4];
        #pragma unroll
        for (int mi = 0; mi < 4; mi++)
            ldsm_x4(af[mi][0], af[mi][1], af[mi][2], af[mi][3], soff + aoff[mi] + kk * 2);
        uint32_t bf[8][2];
        #pragma unroll
        for (int np = 0; np < 4; np++)
            ldsm_x4(bf[2 * np][0], bf[2 * np][1], bf[2 * np + 1][0], bf[2 * np + 1][1],
                    soff + boff[np] + kk * 2);
        #pragma unroll
        for (int mi = 0; mi < 4; mi++)
            #pragma unroll
            for (int ni = 0; ni < 8; ni++)
                mma_fp16(acc[mi][ni],
                         af[mi][0], af[mi][1], af[mi][2], af[mi][3],
                         bf[ni][0], bf[ni][1]);
    }
}

// shared mainloop prologue+loop (declares tid/lane/warp/wr/wc/g/r8/gid/tig/row0/col0/acc)
#define GEMM_BODY()                                                                \
    extern __shared__ uint32_t sm[];                                               \
    int tid  = threadIdx.x;                                                        \
    int lane = tid & 31;                                                           \
    int warp = tid >> 5;                                                           \
    int wr = warp >> 1, wc = warp & 1;                                             \
    int g  = lane >> 3, r8 = lane & 7;                                             \
    int gid = lane >> 2, tig = lane & 3;                                           \
    int row0 = blockIdx.y * 128;                                                   \
    int col0 = blockIdx.x * 128;                                                   \
    uint32_t sbase = (uint32_t)__cvta_generic_to_shared(sm);                       \
    uint32_t aoff[4], boff[4];                                                     \
    _Pragma("unroll")                                                              \
    for (int mi = 0; mi < 4; mi++) {                                               \
        int row = wr * 64 + mi * 16 + ((g & 1) << 3) + r8;                         \
        aoff[mi] = (row * SROWH + ((g >> 1) << 3)) * 2;                            \
    }                                                                              \
    _Pragma("unroll")                                                              \
    for (int np = 0; np < 4; np++) {                                               \
        int row = 128 + wc * 64 + np * 16 + ((g >> 1) << 3) + r8;                  \
        boff[np] = (row * SROWH + ((g & 1) << 3)) * 2;                             \
    }                                                                              \
    float acc[4][8][4];                                                            \
    _Pragma("unroll")                                                              \
    for (int mi = 0; mi < 4; mi++)                                                 \
        _Pragma("unroll")                                                          \
        for (int ni = 0; ni < 8; ni++)                                             \
            _Pragma("unroll")                                                      \
            for (int t = 0; t < 4; t++) acc[mi][ni][t] = 0.0f;                     \
    issue_load(sbase, 0, A, Bt, row0, col0, M, 0, tid);                            \
    asm volatile("cp.async.commit_group;" ::: "memory");                           \
    issue_load(sbase, 1, A, Bt, row0, col0, M, 32, tid);                           \
    asm volatile("cp.async.commit_group;" ::: "memory");                           \
    _Pragma("unroll")                                                              \
    for (int it = 0; it < 8; it++) {                                               \
        asm volatile("cp.async.wait_group 1;" ::: "memory");                       \
        __syncthreads();                                                           \
        compute_stage(sbase + (it % 3) * STGH_BYTES, aoff, boff, acc);             \
        if (it + 2 < 8)                                                            \
            issue_load(sbase, (it + 2) % 3, A, Bt, row0, col0, M, (it + 2) * 32, tid); \
        asm volatile("cp.async.commit_group;" ::: "memory");                       \
    }

template <bool HALF_OUT>
__global__ void __launch_bounds__(128) gemm_fp16(const __half* __restrict__ A,
                                                 const __half* __restrict__ Bt,
                                                 const float* __restrict__ bias,
                                                 void* __restrict__ Cv, int M, int N)
{
    GEMM_BODY();
    float*  Cf = (float*)Cv;
    __half* Ch = (__half*)Cv;
    #pragma unroll
    for (int mi = 0; mi < 4; mi++) {
        int rbase = row0 + wr * 64 + mi * 16 + gid;
        #pragma unroll
        for (int ni = 0; ni < 8; ni++) {
            int c = col0 + wc * 64 + ni * 8 + 2 * tig;
            float b0 = bias[c], b1 = bias[c + 1];
            if (rbase < M) {
                float v0 = acc[mi][ni][0] + b0, v1 = acc[mi][ni][1] + b1;
                if (HALF_OUT)
                    *reinterpret_cast<__half2*>(Ch + (size_t)rbase * N + c) = __floats2half2_rn(v0, v1);
                else
                    *reinterpret_cast<float2*>(Cf + (size_t)rbase * N + c) = make_float2(v0, v1);
            }
            if (rbase + 8 < M) {
                float v2 = acc[mi][ni][2] + b0, v3 = acc[mi][ni][3] + b1;
                if (HALF_OUT)
                    *reinterpret_cast<__half2*>(Ch + (size_t)(rbase + 8) * N + c) = __floats2half2_rn(v2, v3);
                else
                    *reinterpret_cast<float2*>(Cf + (size_t)(rbase + 8) * N + c) = make_float2(v2, v3);
            }
        }
    }
}

// ---------- leaf GEMM with write-only gate epilogue (permuted WleafT, N=1024) ----
__global__ void __launch_bounds__(128) gemm_leaf_gate(const __half* __restrict__ A,
                                                      const __half* __restrict__ Bt,
                                                      float* __restrict__ outH,
                                                      float* __restrict__ outC,
                                                      int M)
{
    GEMM_BODY();
    #pragma unroll
    for (int mi = 0; mi < 4; mi++) {
        int rloc0 = row0 + wr * 64 + mi * 16 + gid;
        #pragma unroll
        for (int s = 0; s < 2; s++) {
            int d = blockIdx.x * 32 + wc * 16 + s * 8 + 2 * tig;
            float bi0 = g_bcat2[d],        bi1 = g_bcat2[d + 1];
            float bo0 = g_bcat2[256 + d],  bo1 = g_bcat2[257 + d];
            float bu0 = g_bcat2[512 + d],  bu1 = g_bcat2[513 + d];
            #pragma unroll
            for (int hrow = 0; hrow < 2; hrow++) {
                int rloc = rloc0 + 8 * hrow;
                int t0 = 2 * hrow, t1 = 2 * hrow + 1;
                float i0 = acc[mi][0 + s][t0] + bi0, i1 = acc[mi][0 + s][t1] + bi1;
                float o0 = acc[mi][2 + s][t0] + bo0, o1 = acc[mi][2 + s][t1] + bo1;
                float u0 = acc[mi][4 + s][t0] + bu0, u1 = acc[mi][4 + s][t1] + bu1;
                float c0 = sigmoidf_(i0) * tanhf(u0);
                float c1 = sigmoidf_(i1) * tanhf(u1);
                float h0 = sigmoidf_(o0) * tanhf(c0);
                float h1 = sigmoidf_(o1) * tanhf(c1);
                size_t base = (size_t)(LEAF_START + rloc) * 256 + d;
                *reinterpret_cast<float2*>(outH + base) = make_float2(h0, h1);
                *reinterpret_cast<float2*>(outC + base) = make_float2(c0, c1);
                *reinterpret_cast<__half2*>(g_hH + base) = __floats2half2_rn(h0, h1);
            }
        }
    }
}

__device__ __forceinline__ float4 load_h4(const __half* p) {
    uint2 raw = *reinterpret_cast<const uint2*>(p);
    __half2 a = *reinterpret_cast<__half2*>(&raw.x);
    __half2 b = *reinterpret_cast<__half2*>(&raw.y);
    float2 fa = __half22float2(a), fb = __half22float2(b);
    return make_float4(fa.x, fa.y, fb.x, fb.y);
}

// ---------------- attention: warp per (node, head) ----------------
__global__ void attn_kernel(int s0)
{
    int j = blockIdx.x;
    int node = s0 + j;
    int w = threadIdx.x >> 5;
    int t = threadIdx.x & 31;
    const float scale = 0.17677669529663687f; // 1/sqrt(32)
    float qv = __half2float(g_xioufq[(size_t)node * 1280 + 1024 + w * 32 + t]);
    float logit[4];
    #pragma unroll
    for (int k = 0; k < 4; k++) {
        float kk = __half2float(g_kv[(size_t)(4 * j + k) * 512 + w * 32 + t]);
        float p = qv * kk;
        #pragma unroll
        for (int off = 16; off; off >>= 1) p += __shfl_xor_sync(0xffffffffu, p, off);
        logit[k] = p * scale;
    }
    float m = fmaxf(fmaxf(logit[0], logit[1]), fmaxf(logit[2], logit[3]));
    float e[4], s = 0.f;
    #pragma unroll
    for (int k = 0; k < 4; k++) { e[k] = expf(logit[k] - m); s += e[k]; }
    float inv = 1.0f / s;
    float o = 0.f;
    #pragma unroll
    for (int k = 0; k < 4; k++)
        o += e[k] * inv * __half2float(g_kv[(size_t)(4 * j + k) * 512 + 256 + w * 32 + t]);
    g_aoutH[(size_t)j * 256 + w * 32 + t] = __float2half(o);
}

// ---------------- internal-level gates ----------------
__global__ void gate_kernel(float* __restrict__ outH, float* __restrict__ outC,
                            int s0, int cs, int n)
{
    int t  = threadIdx.x;
    int jj = blockIdx.x * 4 + (t >> 6);
    if (jj >= n) return;
    int d  = (t & 63) * 4;
    int node = s0 + jj;
    const __half* xr = g_xioufq + (size_t)node * 1280;
    const __half* hr = g_hu + (size_t)jj * 1024;
    float4 i4 = load_h4(xr + d);
    float4 o4 = load_h4(xr + 256 + d);
    float4 u4 = load_h4(xr + 512 + d);
    float4 f4 = load_h4(xr + 768 + d);
    float4 hi = load_h4(hr + d);
    float4 ho = load_h4(hr + 256 + d);
    float4 hu4 = load_h4(hr + 512 + d);
    float4 hf = load_h4(hr + 768 + d);
    float4 cs4 = make_float4(0.f, 0.f, 0.f, 0.f);
    #pragma unroll
    for (int k = 0; k < 4; k++) {
        float4 cc = *reinterpret_cast<const float4*>(outC + (size_t)(cs + 4 * jj + k) * 256 + d);
        cs4.x += cc.x; cs4.y += cc.y; cs4.z += cc.z; cs4.w += cc.w;
    }
    float4 c4, h4;
    __half hh[4];
    #pragma unroll
    for (int q = 0; q < 4; q++) {
        float i = (&i4.x)[q] + (&hi.x)[q];
        float o = (&o4.x)[q] + (&ho.x)[q];
        float u = (&u4.x)[q] + (&hu4.x)[q];
        float f = sigmoidf_((&f4.x)[q] + (&hf.x)[q]);
        float c = sigmoidf_(i) * tanhf(u) + f * (&cs4.x)[q];
        float h = sigmoidf_(o) * tanhf(c);
        (&c4.x)[q] = c; (&h4.x)[q] = h; hh[q] = __float2half(h);
    }
    size_t base = (size_t)node * 256 + d;
    *reinterpret_cast<float4*>(outH + base) = h4;
    *reinterpret_cast<float4*>(outC + base) = c4;
    *reinterpret_cast<uint2*>(g_hH + base) = *reinterpret_cast<uint2*>(hh);
}

// ---------------- host launch ----------------
extern "C" void kernel_launch(void* const* d_in, const int* in_sizes, int n_in,
                              void* d_out, int out_size)
{
    const float* x      = (const float*)d_in[0];
    const float* W_iou  = (const float*)d_in[1];
    const float* b_iou  = (const float*)d_in[2];
    const float* W_f    = (const float*)d_in[3];
    const float* b_f    = (const float*)d_in[4];
    const float* Wq     = (const float*)d_in[5];
    const float* bq     = (const float*)d_in[6];
    const float* Wk     = (const float*)d_in[7];
    const float* bk     = (const float*)d_in[8];
    const float* Wv     = (const float*)d_in[9];
    const float* bv     = (const float*)d_in[10];
    const float* Wl     = (const float*)d_in[11];
    const float* bl     = (const float*)d_in[12];
    const float* Uiou_w = (const float*)d_in[13];
    const float* Uiou_b = (const float*)d_in[14];
    const float* Uf_w   = (const float*)d_in[15];
    const float* Uf_b   = (const float*)d_in[16];

    float* outH = (float*)d_out;
    float* outC = outH + (size_t)N_NODES * 256;

    static bool attr_set = false;
    if (!attr_set) {
        cudaFuncSetAttribute(gemm_fp16<false>, cudaFuncAttributeMaxDynamicSharedMemorySize, GEMM_SMEM);
        cudaFuncSetAttribute(gemm_fp16<true>,  cudaFuncAttributeMaxDynamicSharedMemorySize, GEMM_SMEM);
        cudaFuncSetAttribute(gemm_leaf_gate,   cudaFuncAttributeMaxDynamicSharedMemorySize, GEMM_SMEM);
        attr_set = true;
    }

    __half *p_xH, *p_hH, *p_aoutH, *p_W2, *p_Wleaf, *p_Wkv, *p_Uc, *p_WlR, *p_WcT;
    __half *p_xioufq, *p_kv, *p_hu;
    float *p_b2, *p_bkv, *p_WcR, *p_bc, *p_zero;
    cudaGetSymbolAddress((void**)&p_xH,     g_xH);
    cudaGetSymbolAddress((void**)&p_hH,     g_hH);
    cudaGetSymbolAddress((void**)&p_aoutH,  g_aoutH);
    cudaGetSymbolAddress((void**)&p_xioufq, g_xioufq);
    cudaGetSymbolAddress((void**)&p_kv,     g_kv);
    cudaGetSymbolAddress((void**)&p_hu,     g_hu);
    cudaGetSymbolAddress((void**)&p_W2,     g_Wcat2T);
    cudaGetSymbolAddress((void**)&p_b2,     g_bcat2);
    cudaGetSymbolAddress((void**)&p_Wleaf,  g_WleafT);
    cudaGetSymbolAddress((void**)&p_Wkv,    g_WkvT);
    cudaGetSymbolAddress((void**)&p_bkv,    g_bkv);
    cudaGetSymbolAddress((void**)&p_Uc,     g_UcatT);
    cudaGetSymbolAddress((void**)&p_WlR,    g_WlR);
    cudaGetSymbolAddress((void**)&p_WcR,    g_WcombRaw);
    cudaGetSymbolAddress((void**)&p_WcT,    g_WcombT);
    cudaGetSymbolAddress((void**)&p_bc,     g_bcomb);
    cudaGetSymbolAddress((void**)&p_zero,   g_zero);

    static const int starts[LEVELS + 1] =
        {0, 1, 5, 21, 85, 341, 1365, 5461, 21845, 87381};

    pack_weights<<<(256 * 1280 + 255) / 256, 256>>>(
        W_iou, b_iou, W_f, b_f, Wq, bq, Wk, bk, Wv, bv, Wl, bl, Uiou_w, Uf_w);

    // [Wcomb; bl@U] = [Wl; bl] @ U  (257 x 1024 fp32), then transpose+convert + bcomb
    {
        dim3 grid(1024 / 128, 3);
        gemm_fp16<false><<<grid, 128, GEMM_SMEM>>>(p_WlR, p_Uc, p_zero, p_WcR, 257, 1024);
    }
    finish_comb<<<(256 * 1024 + 255) / 256, 256>>>(Uiou_b, Uf_b);

    convert_x_kernel<<<(N_NODES * 64 + 255) / 256, 256>>>(x);

    // fused leaf GEMM + gates (permuted weights, N=1024, write-only epilogue)
    {
        dim3 grid(8, LEAF_N / 128);
        gemm_leaf_gate<<<grid, 128, GEMM_SMEM>>>(p_xH + (size_t)LEAF_START * 256,
                                                 p_Wleaf, outH, outC, LEAF_N);
    }
    // internal iou|f|q (N=1280, fp16 out)
    {
        dim3 grid(1280 / 128, (N_INTERNAL + 127) / 128);
        gemm_fp16<true><<<grid, 128, GEMM_SMEM>>>(p_xH, p_W2, p_b2, p_xioufq, N_INTERNAL, 1280);
    }

    for (int l = LEVELS - 2; l >= 0; --l) {
        int n  = 1 << (2 * l);
        int s0 = starts[l];
        int cs = starts[l + 1];
        int nc = 4 * n;

        {
            dim3 grid(512 / 128, (nc + 127) / 128);
            gemm_fp16<true><<<grid, 128, GEMM_SMEM>>>(p_hH + (size_t)cs * 256,
                                                      p_Wkv, p_bkv, p_kv, nc, 512);
        }
        attn_kernel<<<n, 256>>>(s0);
        {
            dim3 grid(1024 / 128, (n + 127) / 128);
            gemm_fp16<true><<<grid, 128, GEMM_SMEM>>>(p_aoutH, p_WcT, p_bc, p_hu, n, 1024);
        }
        gate_kernel<<<(n + 3) / 4, 256>>>(outH, outC, s0, cs, n);
    }
}